// round 4
// baseline (speedup 1.0000x reference)
#include <cuda_runtime.h>
#include <math.h>

#define BQ   512
#define TQ   1024
#define DQ   4
#define HQ   64
#define G4   256          // 4*H
#define NB   4            // batches per recurrent block
#define NCLS 1098
#define FB   4            // batches per final-head block

typedef unsigned long long ull;

// ---------------- scratch (static device allocations only) ----------------
__device__ float g_g1[2][(size_t)BQ * TQ * G4];   // layer-1 gate preactivations per dir
__device__ float g_h0[(size_t)BQ * TQ * 128];     // layer-0 bidir output, [B][T][128]
__device__ float g_h1last[BQ * 128];              // gathered last timestep of layer 1
__device__ float g_WT[2][128 * G4];               // Wih1 transposed: [dir][k][gate]

// ---------------- f32x2 packed-math helpers ----------------
__device__ __forceinline__ ull pk2(float lo, float hi) {
    ull r; asm("mov.b64 %0,{%1,%2};" : "=l"(r) : "f"(lo), "f"(hi)); return r;
}
__device__ __forceinline__ void upk2(ull v, float& lo, float& hi) {
    asm("mov.b64 {%0,%1},%2;" : "=f"(lo), "=f"(hi) : "l"(v));
}
__device__ __forceinline__ ull ffma2(ull a, ull b, ull c) {
    ull d; asm("fma.rn.f32x2 %0,%1,%2,%3;" : "=l"(d) : "l"(a), "l"(b), "l"(c)); return d;
}
__device__ __forceinline__ float tanh_fast(float x) {
    float y; asm("tanh.approx.f32 %0,%1;" : "=f"(y) : "f"(x)); return y;
}
__device__ __forceinline__ float sig_fast(float x) {
    return fmaf(0.5f, tanh_fast(0.5f * x), 0.5f);
}

// block (0..255) -> sorted group id: pairs co-resident blocks (bid, bid+148)
// with (long, short) sequence groups so per-SM step totals are ~balanced.
__device__ __forceinline__ void block_to_group(int bid, int& dir, int& xb) {
    int j = (bid < 148) ? bid : (403 - bid);
    dir = j & 1;
    xb  = j >> 1;
}

// gpre exchange layout: idx(s, b, u) = s*296 + b*72 + u  (bank-conflict free)
#define GPRE_S 296
#define GPRE_B 72
#define HS_PAD 72

// =====================================================================
// Layer 0: bidirectional LSTM, warp-local gate exchange, 1 barrier/step.
// lane l: gate-type q=l>>3, unit u=8*warp+(l&7); gate row gr=q*64+u.
// Phase-B role: (batch q, unit u) — all 4 gates of u are in this warp.
// =====================================================================
__global__ void __launch_bounds__(256, 2)
lstm_l0_kernel(const float* __restrict__ x, const int* __restrict__ lens,
               const float* __restrict__ WihF, const float* __restrict__ WhhF,
               const float* __restrict__ bihF, const float* __restrict__ bhhF,
               const float* __restrict__ WihB, const float* __restrict__ WhhB,
               const float* __restrict__ bihB, const float* __restrict__ bhhB)
{
    int dir, xb;
    block_to_group(blockIdx.x, dir, xb);
    const int bbase = xb * NB;
    const int tid = threadIdx.x;
    const int w   = tid >> 5;
    const int l   = tid & 31;
    const int q   = l >> 3;            // gate type (A) / batch (B)
    const int u   = w * 8 + (l & 7);   // hidden unit
    const int gr  = q * 64 + u;        // gate row

    const float* Wih = dir ? WihB : WihF;
    const float* Whh = dir ? WhhB : WhhF;
    const float* bih = dir ? bihB : bihF;
    const float* bhh = dir ? bhhB : bhhF;

    ull whh2[HQ / 2];
    {
        const ull* wsrc = reinterpret_cast<const ull*>(Whh + (size_t)gr * HQ);
#pragma unroll
        for (int k = 0; k < HQ / 2; ++k) whh2[k] = wsrc[k];
    }
    float wih[DQ];
#pragma unroll
    for (int k = 0; k < DQ; ++k) wih[k] = Wih[gr * DQ + k];
    const float bias = bih[gr] + bhh[gr];

    __shared__ __align__(16) float hsh[2][NB][HS_PAD];
    __shared__ float  gpre[4 * GPRE_S];
    __shared__ float4 xs[2][NB];
    __shared__ int    lsh[NB];

    if (tid < NB) {
        int len = lens[bbase + tid];
        lsh[tid] = len;
        int tt = dir ? (len - 1) : 0;
        xs[0][tid] = reinterpret_cast<const float4*>(x)[(size_t)(bbase + tid) * TQ + tt];
    }
    hsh[0][q][u] = 0.0f;
    float c = 0.0f;
    __syncthreads();

    const int maxlen = lsh[0];

    for (int t = 0; t < maxlen; ++t) {
        float4 xn = make_float4(0.f, 0.f, 0.f, 0.f);
        if (tid < NB) {
            int tn  = (t + 1 < maxlen) ? (t + 1) : t;
            int len = lsh[tid];
            int tt  = tn;
            if (dir) tt = (tn < len) ? (len - 1 - tn) : tn;
            xn = reinterpret_cast<const float4*>(x)[(size_t)(bbase + tid) * TQ + tt];
        }

        // ---- phase A: gate preactivations
        float acc[NB];
#pragma unroll
        for (int b = 0; b < NB; ++b) {
            float4 xv = xs[t & 1][b];
            float base = bias + wih[0] * xv.x + wih[1] * xv.y
                              + wih[2] * xv.z + wih[3] * xv.w;
            const ulonglong2* h2 = reinterpret_cast<const ulonglong2*>(&hsh[t & 1][b][0]);
            ull a0 = 0ull, a1 = 0ull;
#pragma unroll
            for (int kk = 0; kk < HQ / 4; ++kk) {
                ulonglong2 hv = h2[kk];
                a0 = ffma2(whh2[2 * kk],     hv.x, a0);
                a1 = ffma2(whh2[2 * kk + 1], hv.y, a1);
            }
            float l0, u0, l1, u1;
            upk2(a0, l0, u0); upk2(a1, l1, u1);
            acc[b] = base + ((l0 + u0) + (l1 + u1));
        }
#pragma unroll
        for (int b = 0; b < NB; ++b) gpre[q * GPRE_S + b * GPRE_B + u] = acc[b];
        __syncwarp();

        // ---- phase B: pointwise for (batch q, unit u) — warp-local reads
        {
            float gi = gpre[0 * GPRE_S + q * GPRE_B + u];
            float gf = gpre[1 * GPRE_S + q * GPRE_B + u];
            float gc = gpre[2 * GPRE_S + q * GPRE_B + u];
            float go = gpre[3 * GPRE_S + q * GPRE_B + u];
            float si = sig_fast(gi);
            float sf = sig_fast(gf);
            float tg = tanh_fast(gc);
            float so = sig_fast(go);
            c = sf * c + si * tg;
            float h = so * tanh_fast(c);
            hsh[(t + 1) & 1][q][u] = h;

            int len = lsh[q];
            int ts  = t;
            if (dir) ts = (t < len) ? (len - 1 - t) : t;
            g_h0[((size_t)(bbase + q) * TQ + ts) * 128 + dir * HQ + u] = h;
        }
        if (tid < NB) xs[(t + 1) & 1][tid] = xn;
        __syncthreads();
    }
}

// =====================================================================
// Wih1 transpose pre-kernel: g_WT[dir][k][g] = Wih1_dir[g][k]
// =====================================================================
__global__ void transpose_w_kernel(const float* __restrict__ WihF,
                                   const float* __restrict__ WihB)
{
    const float* W  = blockIdx.x ? WihB : WihF;
    float*       WT = g_WT[blockIdx.x];
    const int g = threadIdx.x;               // 0..255
    const float4* wrow = reinterpret_cast<const float4*>(W + (size_t)g * 128);
#pragma unroll
    for (int k4 = 0; k4 < 32; ++k4) {
        float4 v = wrow[k4];
        WT[(4 * k4 + 0) * G4 + g] = v.x;
        WT[(4 * k4 + 1) * G4 + g] = v.y;
        WT[(4 * k4 + 2) * G4 + g] = v.z;
        WT[(4 * k4 + 3) * G4 + g] = v.w;
    }
}

// =====================================================================
// Layer-1 gate GEMM, packed f32x2, k-major duplicated A tile.
// 64x256 tile, 8x8 microtile (8 rows x 4 col-pairs), GM_KC=16.
// Tiles entirely past the sequence end exit immediately.
// =====================================================================
#define GM_ROWS 64
#define GM_KC   16

__global__ void __launch_bounds__(256, 2)
gates1_gemm_kernel(const int* __restrict__ lens,
                   const float* __restrict__ bihF, const float* __restrict__ bhhF,
                   const float* __restrict__ bihB, const float* __restrict__ bhhB)
{
    const int dir   = blockIdx.z;
    const int b     = blockIdx.y;
    const int tbase = blockIdx.x * GM_ROWS;

    const int len = lens[b];
    if (tbase >= len) return;                 // rows >= len are never consumed

    const int tid = threadIdx.x;
    const int tx  = tid & 31, ty = tid >> 5;

    const float* bih = dir ? bihB : bihF;
    const float* bhh = dir ? bhhB : bhhF;
    const float* WT  = g_WT[dir];

    __shared__ ull   As2T[GM_KC][GM_ROWS + 2];     // [k][row], (v,v) pairs
    __shared__ float Ws[GM_KC][G4];                // [k][gate]

    ull acc2[8][4];
#pragma unroll
    for (int r = 0; r < 8; ++r)
#pragma unroll
        for (int cc = 0; cc < 4; ++cc) acc2[r][cc] = 0ull;

    const float* h0b = g_h0 + (size_t)b * TQ * 128;

    for (int k0 = 0; k0 < 128; k0 += GM_KC) {
        // A tile: 64 rows x 16 k, one float4 per thread, stored dup'd k-major
        {
            int r  = tid >> 2, kq = tid & 3;
            int srow = tbase + r;
            if (dir) srow = (srow < len) ? (len - 1 - srow) : srow;
            float4 v = *reinterpret_cast<const float4*>(h0b + (size_t)srow * 128 + k0 + 4 * kq);
            As2T[4 * kq + 0][r] = pk2(v.x, v.x);
            As2T[4 * kq + 1][r] = pk2(v.y, v.y);
            As2T[4 * kq + 2][r] = pk2(v.z, v.z);
            As2T[4 * kq + 3][r] = pk2(v.w, v.w);
        }
        // W tile from pre-transposed WT: coalesced float4 in, STS.128 out
#pragma unroll
        for (int i = 0; i < 4; ++i) {
            int idx = tid + 256 * i;               // 0..1023 float4 slots
            int k   = idx >> 6, c4 = idx & 63;
            float4 v = *reinterpret_cast<const float4*>(WT + (size_t)(k0 + k) * G4 + 4 * c4);
            *reinterpret_cast<float4*>(&Ws[k][4 * c4]) = v;
        }
        __syncthreads();

#pragma unroll
        for (int k = 0; k < GM_KC; ++k) {
            const ulonglong2* adp = reinterpret_cast<const ulonglong2*>(&As2T[k][ty * 8]);
            ulonglong2 ad01 = adp[0], ad23 = adp[1], ad45 = adp[2], ad67 = adp[3];
            ull ad[8] = { ad01.x, ad01.y, ad23.x, ad23.y, ad45.x, ad45.y, ad67.x, ad67.y };
            const ulonglong2* wp = reinterpret_cast<const ulonglong2*>(&Ws[k][0]);
            ulonglong2 w01 = wp[tx];               // cols 4tx .. 4tx+3
            ulonglong2 w23 = wp[tx + 32];          // cols 128+4tx .. 128+4tx+3
#pragma unroll
            for (int r = 0; r < 8; ++r) {
                acc2[r][0] = ffma2(ad[r], w01.x, acc2[r][0]);
                acc2[r][1] = ffma2(ad[r], w01.y, acc2[r][1]);
                acc2[r][2] = ffma2(ad[r], w23.x, acc2[r][2]);
                acc2[r][3] = ffma2(ad[r], w23.y, acc2[r][3]);
            }
        }
        __syncthreads();
    }

    // epilogue: bias add + coalesced float4 stores
    const float4* bi4 = reinterpret_cast<const float4*>(bih);
    const float4* bh4 = reinterpret_cast<const float4*>(bhh);
    float4 ba = bi4[tx],      bb = bh4[tx];
    float4 bv1 = make_float4(ba.x + bb.x, ba.y + bb.y, ba.z + bb.z, ba.w + bb.w);
    ba = bi4[tx + 32]; bb = bh4[tx + 32];
    float4 bv2 = make_float4(ba.x + bb.x, ba.y + bb.y, ba.z + bb.z, ba.w + bb.w);

    float* outp = g_g1[dir] + ((size_t)b * TQ + tbase) * G4;
#pragma unroll
    for (int r = 0; r < 8; ++r) {
        int row = ty * 8 + r;
        float l0, u0, l1, u1;
        upk2(acc2[r][0], l0, u0); upk2(acc2[r][1], l1, u1);
        float4 o1 = make_float4(l0 + bv1.x, u0 + bv1.y, l1 + bv1.z, u1 + bv1.w);
        upk2(acc2[r][2], l0, u0); upk2(acc2[r][3], l1, u1);
        float4 o2 = make_float4(l0 + bv2.x, u0 + bv2.y, l1 + bv2.z, u1 + bv2.w);
        *reinterpret_cast<float4*>(outp + (size_t)row * G4 + 4 * tx)       = o1;
        *reinterpret_cast<float4*>(outp + (size_t)row * G4 + 128 + 4 * tx) = o2;
    }
}

// =====================================================================
// Layer 1: recurrent over precomputed gates, warp-local exchange,
// 1 barrier/step. Stores only the final-gather positions.
// =====================================================================
__global__ void __launch_bounds__(256, 2)
lstm_l1_kernel(const int* __restrict__ lens,
               const float* __restrict__ WhhF, const float* __restrict__ WhhB)
{
    int dir, xb;
    block_to_group(blockIdx.x, dir, xb);
    const int bbase = xb * NB;
    const int tid = threadIdx.x;
    const int w   = tid >> 5;
    const int l   = tid & 31;
    const int q   = l >> 3;
    const int u   = w * 8 + (l & 7);
    const int gr  = q * 64 + u;

    const float* Whh = dir ? WhhB : WhhF;
    const float* gin = g_g1[dir];

    ull whh2[HQ / 2];
    {
        const ull* wsrc = reinterpret_cast<const ull*>(Whh + (size_t)gr * HQ);
#pragma unroll
        for (int k = 0; k < HQ / 2; ++k) whh2[k] = wsrc[k];
    }

    __shared__ __align__(16) float hsh[2][NB][HS_PAD];
    __shared__ float gpre[4 * GPRE_S];
    __shared__ int   lsh[NB];

    if (tid < NB) lsh[tid] = lens[bbase + tid];
    hsh[0][q][u] = 0.0f;
    float c = 0.0f;
    __syncthreads();

    const int maxlen = lsh[0];

    float ldc[NB];
#pragma unroll
    for (int b = 0; b < NB; ++b)
        ldc[b] = gin[((size_t)(bbase + b) * TQ) * G4 + gr];

    for (int t = 0; t < maxlen; ++t) {
        float ldn[NB];
        const int tn = (t + 1 < maxlen) ? (t + 1) : t;
#pragma unroll
        for (int b = 0; b < NB; ++b)
            ldn[b] = gin[((size_t)(bbase + b) * TQ + tn) * G4 + gr];

        // ---- phase A
        float acc[NB];
#pragma unroll
        for (int b = 0; b < NB; ++b) {
            const ulonglong2* h2 = reinterpret_cast<const ulonglong2*>(&hsh[t & 1][b][0]);
            ull a0 = 0ull, a1 = 0ull;
#pragma unroll
            for (int kk = 0; kk < HQ / 4; ++kk) {
                ulonglong2 hv = h2[kk];
                a0 = ffma2(whh2[2 * kk],     hv.x, a0);
                a1 = ffma2(whh2[2 * kk + 1], hv.y, a1);
            }
            float l0, u0, l1, u1;
            upk2(a0, l0, u0); upk2(a1, l1, u1);
            acc[b] = ldc[b] + ((l0 + u0) + (l1 + u1));
        }
#pragma unroll
        for (int b = 0; b < NB; ++b) gpre[q * GPRE_S + b * GPRE_B + u] = acc[b];
        __syncwarp();

        // ---- phase B: (batch q, unit u)
        {
            float gi = gpre[0 * GPRE_S + q * GPRE_B + u];
            float gf = gpre[1 * GPRE_S + q * GPRE_B + u];
            float gc = gpre[2 * GPRE_S + q * GPRE_B + u];
            float go = gpre[3 * GPRE_S + q * GPRE_B + u];
            float si = sig_fast(gi);
            float sf = sig_fast(gf);
            float tg = tanh_fast(gc);
            float so = sig_fast(go);
            c = sf * c + si * tg;
            float h = so * tanh_fast(c);
            hsh[(t + 1) & 1][q][u] = h;

            int  len = lsh[q];
            bool wr  = dir ? (t == 0) : (t == len - 1);
            if (wr)
                g_h1last[(bbase + q) * 128 + dir * HQ + u] = h;
        }
#pragma unroll
        for (int b = 0; b < NB; ++b) ldc[b] = ldn[b];
        __syncthreads();
    }
}

// =====================================================================
// Final head: FB batches per block; class range split in 2 for parallelism.
// =====================================================================
__global__ void __launch_bounds__(256)
final_kernel(const float* __restrict__ Wout, const float* __restrict__ bout,
             float* __restrict__ out)
{
    const int bbase = blockIdx.x * FB;
    const int chalf = blockIdx.y;              // 0 or 1
    __shared__ float hs[FB][128];
    for (int i = threadIdx.x; i < FB * 128; i += 256)
        hs[i >> 7][i & 127] = g_h1last[bbase * 128 + i];
    __syncthreads();

    const int cbeg = chalf * 549;
    const int cend = cbeg + 549;
    for (int cl = cbeg + threadIdx.x; cl < cend; cl += 256) {
        const float4* wv = reinterpret_cast<const float4*>(Wout + (size_t)cl * 128);
        float a[FB];
#pragma unroll
        for (int b = 0; b < FB; ++b) a[b] = bout[cl];
#pragma unroll
        for (int k = 0; k < 32; ++k) {
            float4 v = wv[k];
#pragma unroll
            for (int b = 0; b < FB; ++b) {
                a[b] += hs[b][4 * k + 0] * v.x + hs[b][4 * k + 1] * v.y
                      + hs[b][4 * k + 2] * v.z + hs[b][4 * k + 3] * v.w;
            }
        }
#pragma unroll
        for (int b = 0; b < FB; ++b)
            out[(size_t)(bbase + b) * NCLS + cl] = a[b];
    }
}

// =====================================================================
extern "C" void kernel_launch(void* const* d_in, const int* in_sizes, int n_in,
                              void* d_out, int out_size)
{
    const float* x     = (const float*)d_in[0];
    const int*   lens  = (const int*)  d_in[1];
    const float* Wih0f = (const float*)d_in[2];
    const float* Whh0f = (const float*)d_in[3];
    const float* bih0f = (const float*)d_in[4];
    const float* bhh0f = (const float*)d_in[5];
    const float* Wih0b = (const float*)d_in[6];
    const float* Whh0b = (const float*)d_in[7];
    const float* bih0b = (const float*)d_in[8];
    const float* bhh0b = (const float*)d_in[9];
    const float* Wih1f = (const float*)d_in[10];
    const float* Whh1f = (const float*)d_in[11];
    const float* bih1f = (const float*)d_in[12];
    const float* bhh1f = (const float*)d_in[13];
    const float* Wih1b = (const float*)d_in[14];
    const float* Whh1b = (const float*)d_in[15];
    const float* bih1b = (const float*)d_in[16];
    const float* bhh1b = (const float*)d_in[17];
    const float* Wout  = (const float*)d_in[18];
    const float* bout  = (const float*)d_in[19];

    transpose_w_kernel<<<2, 256>>>(Wih1f, Wih1b);

    lstm_l0_kernel<<<256, 256>>>(x, lens,
                                 Wih0f, Whh0f, bih0f, bhh0f,
                                 Wih0b, Whh0b, bih0b, bhh0b);

    dim3 gg(TQ / GM_ROWS, BQ, 2);
    gates1_gemm_kernel<<<gg, 256>>>(lens, bih1f, bhh1f, bih1b, bhh1b);

    lstm_l1_kernel<<<256, 256>>>(lens, Whh1f, Whh1b);

    dim3 gf(BQ / FB, 2);
    final_kernel<<<gf, 256>>>(Wout, bout, (float*)d_out);
}

// round 5
// speedup vs baseline: 1.0528x; 1.0528x over previous
#include <cuda_runtime.h>
#include <math.h>

#define BQ   512
#define TQ   1024
#define DQ   4
#define HQ   64
#define G4   256          // 4*H
#define NB   4            // batches per recurrent block
#define NCLS 1098
#define FB   4            // batches per final-head block

#define GM_ROWS 64
#define GM_KC   16

#define L0_BLOCKS   256
#define GEMM_BLOCKS 16384      // 16 tiles x 2 dirs x 512 b
#define L1_BLOCKS   256
#define FUSED_GRID  (L0_BLOCKS + GEMM_BLOCKS + L1_BLOCKS)

typedef unsigned long long ull;

// ---------------- scratch (static device allocations only) ----------------
__device__ float g_g1[2][(size_t)BQ * TQ * G4];   // layer-1 gate preactivations per dir
__device__ float g_h0[(size_t)BQ * TQ * 128];     // layer-0 bidir output, [B][T][128]
__device__ float g_h1last[BQ * 128];              // gathered last timestep of layer 1
__device__ float g_WT[2][128 * G4];               // Wih1 transposed: [dir][k][gate]
__device__ int   g_h0done[BQ];                    // per-seq: count of finished l0 dirs
__device__ int   g_t1flag[2][BQ][16];             // per (dir, seq, 64-row tile) gemm-done

// ---------------- f32x2 packed-math helpers ----------------
__device__ __forceinline__ ull pk2(float lo, float hi) {
    ull r; asm("mov.b64 %0,{%1,%2};" : "=l"(r) : "f"(lo), "f"(hi)); return r;
}
__device__ __forceinline__ void upk2(ull v, float& lo, float& hi) {
    asm("mov.b64 {%0,%1},%2;" : "=f"(lo), "=f"(hi) : "l"(v));
}
__device__ __forceinline__ ull ffma2(ull a, ull b, ull c) {
    ull d; asm("fma.rn.f32x2 %0,%1,%2,%3;" : "=l"(d) : "l"(a), "l"(b), "l"(c)); return d;
}
__device__ __forceinline__ float tanh_fast(float x) {
    float y; asm("tanh.approx.f32 %0,%1;" : "=f"(y) : "f"(x)); return y;
}
__device__ __forceinline__ float sig_fast(float x) {
    return fmaf(0.5f, tanh_fast(0.5f * x), 0.5f);
}

__device__ __forceinline__ void spin_until_eq(volatile int* f, int val) {
    while (*f != val) __nanosleep(64);
}

// block (0..255) -> sorted group id: pairs wave-1 co-resident blocks
// (bid, bid+148) with (long, short) sequence groups.
__device__ __forceinline__ void block_to_group(int bid, int& dir, int& xb) {
    int j = (bid < 148) ? bid : (403 - bid);
    dir = j & 1;
    xb  = j >> 1;
}

// ---------------- shared-memory overlays for the fused kernel ----------------
struct L0Smem {
    float  hsh[NB][HQ];
    float  gpre[NB][G4];
    float4 xs[2][NB];
    int    lsh[NB];
};
struct L1Smem {
    float hsh[NB][HQ];
    float gpre[NB][G4];
    int   lsh[NB];
};
struct GSmem {
    ull   As2T[GM_KC][GM_ROWS + 2];   // [k][row], (v,v) pairs, 8448 B
    float Ws[GM_KC][G4];              // [k][gate], 16384 B
};
#define SMEM_BYTES 25088

// =====================================================================
// Layer 0 (device fn): bidirectional LSTM, R3 structure, truncated.
// Sets g_h0done[b] += 1 on completion of each of its 4 sequences.
// =====================================================================
__device__ void l0_fn(unsigned char* sraw, int bid,
                      const float* __restrict__ x, const int* __restrict__ lens,
                      const float* __restrict__ WihF, const float* __restrict__ WhhF,
                      const float* __restrict__ bihF, const float* __restrict__ bhhF,
                      const float* __restrict__ WihB, const float* __restrict__ WhhB,
                      const float* __restrict__ bihB, const float* __restrict__ bhhB)
{
    L0Smem* s = reinterpret_cast<L0Smem*>(sraw);
    int dir, xb;
    block_to_group(bid, dir, xb);
    const int bbase = xb * NB;
    const int g     = threadIdx.x;            // gate row 0..255

    const float* Wih = dir ? WihB : WihF;
    const float* Whh = dir ? WhhB : WhhF;
    const float* bih = dir ? bihB : bihF;
    const float* bhh = dir ? bhhB : bhhF;

    ull whh2[HQ / 2];
    {
        const ull* wsrc = reinterpret_cast<const ull*>(Whh + (size_t)g * HQ);
#pragma unroll
        for (int k = 0; k < HQ / 2; ++k) whh2[k] = wsrc[k];
    }
    float wih[DQ];
#pragma unroll
    for (int k = 0; k < DQ; ++k) wih[k] = Wih[g * DQ + k];
    const float bias = bih[g] + bhh[g];

    const int pb_b = g >> 6, pb_j = g & 63;

    if (g < NB) s->lsh[g] = lens[bbase + g];
    s->hsh[pb_b][pb_j] = 0.0f;
    float c = 0.0f;
    __syncthreads();

    const int maxlen = s->lsh[0];             // lens sorted descending

    if (g < NB) {
        int len = s->lsh[g];
        int tt  = dir ? (len - 1) : 0;
        s->xs[0][g] = reinterpret_cast<const float4*>(x)[(size_t)(bbase + g) * TQ + tt];
    }

    for (int t = 0; t < maxlen; ++t) {
        float4 xn = make_float4(0.f, 0.f, 0.f, 0.f);
        if (g < NB) {
            int tn  = (t + 1 < maxlen) ? (t + 1) : t;
            int len = s->lsh[g];
            int tt  = tn;
            if (dir) tt = (tn < len) ? (len - 1 - tn) : tn;
            xn = reinterpret_cast<const float4*>(x)[(size_t)(bbase + g) * TQ + tt];
        }
        __syncthreads();

        // ---- phase A: gate preactivations (packed f32x2, LDS.128 h reads)
        float acc[NB];
#pragma unroll
        for (int b = 0; b < NB; ++b) {
            float4 xv = s->xs[t & 1][b];
            float base = bias + wih[0] * xv.x + wih[1] * xv.y
                              + wih[2] * xv.z + wih[3] * xv.w;
            const ulonglong2* h2 = reinterpret_cast<const ulonglong2*>(&s->hsh[b][0]);
            ull a0 = 0ull, a1 = 0ull;
#pragma unroll
            for (int kk = 0; kk < HQ / 4; ++kk) {
                ulonglong2 hv = h2[kk];
                a0 = ffma2(whh2[2 * kk],     hv.x, a0);
                a1 = ffma2(whh2[2 * kk + 1], hv.y, a1);
            }
            float l0v, u0, l1v, u1;
            upk2(a0, l0v, u0); upk2(a1, l1v, u1);
            acc[b] = base + ((l0v + u0) + (l1v + u1));
        }
#pragma unroll
        for (int b = 0; b < NB; ++b) s->gpre[b][g] = acc[b];
        __syncthreads();

        // ---- phase B: pointwise cell update for (pb_b, pb_j)
        {
            float gi = s->gpre[pb_b][pb_j];
            float gf = s->gpre[pb_b][HQ + pb_j];
            float gc = s->gpre[pb_b][2 * HQ + pb_j];
            float go = s->gpre[pb_b][3 * HQ + pb_j];
            float si = sig_fast(gi);
            float sf = sig_fast(gf);
            float tg = tanh_fast(gc);
            float so = sig_fast(go);
            c = sf * c + si * tg;
            float h = so * tanh_fast(c);
            s->hsh[pb_b][pb_j] = h;

            int len = s->lsh[pb_b];
            int ts  = t;
            if (dir) ts = (t < len) ? (len - 1 - t) : t;
            g_h0[((size_t)(bbase + pb_b) * TQ + ts) * 128 + dir * HQ + pb_j] = h;
        }
        if (g < NB) s->xs[(t + 1) & 1][g] = xn;
    }

    // publish: all h0 rows for these 4 sequences are written
    __threadfence();
    __syncthreads();
    if (g < NB) atomicAdd(&g_h0done[bbase + g], 1);
}

// =====================================================================
// Gates GEMM (device fn): waits for h0done[b]==2, computes 64x256 tile,
// sets g_t1flag[dir][b][tile] = 1.
// =====================================================================
__device__ void gemm_fn(unsigned char* sraw, int gbid, const int* __restrict__ lens,
                        const float* __restrict__ bihF, const float* __restrict__ bhhF,
                        const float* __restrict__ bihB, const float* __restrict__ bhhB)
{
    GSmem* s = reinterpret_cast<GSmem*>(sraw);
    const int tile = gbid >> 10;           // 0..15 (tile-major: tile 0 first)
    const int rem  = gbid & 1023;
    const int dir  = rem >> 9;
    const int b    = 511 - (rem & 511);    // short sequences (ready earliest) first
    const int tbase = tile * GM_ROWS;

    const int len = lens[b];
    if (tbase >= len) return;              // rows >= len are never consumed

    const int tid = threadIdx.x;
    const int tx  = tid & 31, ty = tid >> 5;

    // wait for both l0 directions of sequence b
    if (tid == 0) spin_until_eq(&g_h0done[b], 2);
    __syncthreads();
    __threadfence();

    const float* bih = dir ? bihB : bihF;
    const float* bhh = dir ? bhhB : bhhF;
    const float* WT  = g_WT[dir];

    ull acc2[8][4];
#pragma unroll
    for (int r = 0; r < 8; ++r)
#pragma unroll
        for (int cc = 0; cc < 4; ++cc) acc2[r][cc] = 0ull;

    const float* h0b = g_h0 + (size_t)b * TQ * 128;

    for (int k0 = 0; k0 < 128; k0 += GM_KC) {
        // A tile: 64 rows x 16 k, one float4 per thread, stored dup'd k-major
        {
            int r  = tid >> 2, kq = tid & 3;
            int srow = tbase + r;
            if (dir) srow = (srow < len) ? (len - 1 - srow) : srow;
            float4 v = *reinterpret_cast<const float4*>(h0b + (size_t)srow * 128 + k0 + 4 * kq);
            s->As2T[4 * kq + 0][r] = pk2(v.x, v.x);
            s->As2T[4 * kq + 1][r] = pk2(v.y, v.y);
            s->As2T[4 * kq + 2][r] = pk2(v.z, v.z);
            s->As2T[4 * kq + 3][r] = pk2(v.w, v.w);
        }
        // W tile from pre-transposed WT
#pragma unroll
        for (int i = 0; i < 4; ++i) {
            int idx = tid + 256 * i;               // 0..1023 float4 slots
            int k   = idx >> 6, c4 = idx & 63;
            float4 v = *reinterpret_cast<const float4*>(WT + (size_t)(k0 + k) * G4 + 4 * c4);
            *reinterpret_cast<float4*>(&s->Ws[k][4 * c4]) = v;
        }
        __syncthreads();

#pragma unroll
        for (int k = 0; k < GM_KC; ++k) {
            const ulonglong2* adp = reinterpret_cast<const ulonglong2*>(&s->As2T[k][ty * 8]);
            ulonglong2 ad01 = adp[0], ad23 = adp[1], ad45 = adp[2], ad67 = adp[3];
            ull ad[8] = { ad01.x, ad01.y, ad23.x, ad23.y, ad45.x, ad45.y, ad67.x, ad67.y };
            const ulonglong2* wp = reinterpret_cast<const ulonglong2*>(&s->Ws[k][0]);
            ulonglong2 w01 = wp[tx];
            ulonglong2 w23 = wp[tx + 32];
#pragma unroll
            for (int r = 0; r < 8; ++r) {
                acc2[r][0] = ffma2(ad[r], w01.x, acc2[r][0]);
                acc2[r][1] = ffma2(ad[r], w01.y, acc2[r][1]);
                acc2[r][2] = ffma2(ad[r], w23.x, acc2[r][2]);
                acc2[r][3] = ffma2(ad[r], w23.y, acc2[r][3]);
            }
        }
        __syncthreads();
    }

    // epilogue: bias add + coalesced float4 stores
    const float4* bi4 = reinterpret_cast<const float4*>(bih);
    const float4* bh4 = reinterpret_cast<const float4*>(bhh);
    float4 ba = bi4[tx],      bb = bh4[tx];
    float4 bv1 = make_float4(ba.x + bb.x, ba.y + bb.y, ba.z + bb.z, ba.w + bb.w);
    ba = bi4[tx + 32]; bb = bh4[tx + 32];
    float4 bv2 = make_float4(ba.x + bb.x, ba.y + bb.y, ba.z + bb.z, ba.w + bb.w);

    float* outp = g_g1[dir] + ((size_t)b * TQ + tbase) * G4;
#pragma unroll
    for (int r = 0; r < 8; ++r) {
        int row = ty * 8 + r;
        float l0v, u0, l1v, u1;
        upk2(acc2[r][0], l0v, u0); upk2(acc2[r][1], l1v, u1);
        float4 o1 = make_float4(l0v + bv1.x, u0 + bv1.y, l1v + bv1.z, u1 + bv1.w);
        upk2(acc2[r][2], l0v, u0); upk2(acc2[r][3], l1v, u1);
        float4 o2 = make_float4(l0v + bv2.x, u0 + bv2.y, l1v + bv2.z, u1 + bv2.w);
        *reinterpret_cast<float4*>(outp + (size_t)row * G4 + 4 * tx)       = o1;
        *reinterpret_cast<float4*>(outp + (size_t)row * G4 + 128 + 4 * tx) = o2;
    }

    // publish this tile
    __threadfence();
    __syncthreads();
    if (tid == 0) *((volatile int*)&g_t1flag[dir][b][tile]) = 1;
}

// =====================================================================
// Layer 1 (device fn): R3 structure + per-tile flag waits.
// =====================================================================
__device__ void l1_fn(unsigned char* sraw, int j, const int* __restrict__ lens,
                      const float* __restrict__ WhhF, const float* __restrict__ WhhB)
{
    L1Smem* s = reinterpret_cast<L1Smem*>(sraw);
    const int dir   = j & 1;               // group 0 (longest) first: LPT scheduling
    const int xb    = j >> 1;
    const int bbase = xb * NB;
    const int g     = threadIdx.x;

    const float* Whh = dir ? WhhB : WhhF;
    const float* gin = g_g1[dir];

    ull whh2[HQ / 2];
    {
        const ull* wsrc = reinterpret_cast<const ull*>(Whh + (size_t)g * HQ);
#pragma unroll
        for (int k = 0; k < HQ / 2; ++k) whh2[k] = wsrc[k];
    }

    const int pb_b = g >> 6, pb_j = g & 63;
    if (g < NB) s->lsh[g] = lens[bbase + g];
    s->hsh[pb_b][pb_j] = 0.0f;
    float c = 0.0f;
    __syncthreads();

    const int maxlen = s->lsh[0];

    // wait for tile 0 of all 4 sequences (t=0 always valid: len >= 1)
    if (g < NB) spin_until_eq(&g_t1flag[dir][bbase + g][0], 1);
    __syncthreads();
    __threadfence();

    float ldc[NB];
#pragma unroll
    for (int b = 0; b < NB; ++b)
        ldc[b] = gin[((size_t)(bbase + b) * TQ) * G4 + g];

    for (int t = 0; t < maxlen; ++t) {
        const int tn = (t + 1 < maxlen) ? (t + 1) : t;

        // crossing into a new 64-row tile: wait for its gemm flags
        if (tn == t + 1 && (tn & 63) == 0) {
            if (g < NB && tn < s->lsh[g])
                spin_until_eq(&g_t1flag[dir][bbase + g][tn >> 6], 1);
            __syncthreads();
            __threadfence();
        }

        float ldn[NB];
#pragma unroll
        for (int b = 0; b < NB; ++b)
            ldn[b] = gin[((size_t)(bbase + b) * TQ + tn) * G4 + g];

        __syncthreads();

        // ---- phase A
        float acc[NB];
#pragma unroll
        for (int b = 0; b < NB; ++b) {
            const ulonglong2* h2 = reinterpret_cast<const ulonglong2*>(&s->hsh[b][0]);
            ull a0 = 0ull, a1 = 0ull;
#pragma unroll
            for (int kk = 0; kk < HQ / 4; ++kk) {
                ulonglong2 hv = h2[kk];
                a0 = ffma2(whh2[2 * kk],     hv.x, a0);
                a1 = ffma2(whh2[2 * kk + 1], hv.y, a1);
            }
            float l0v, u0, l1v, u1;
            upk2(a0, l0v, u0); upk2(a1, l1v, u1);
            acc[b] = ldc[b] + ((l0v + u0) + (l1v + u1));
        }
#pragma unroll
        for (int b = 0; b < NB; ++b) s->gpre[b][g] = acc[b];
        __syncthreads();

        // ---- phase B
        {
            float gi = s->gpre[pb_b][pb_j];
            float gf = s->gpre[pb_b][HQ + pb_j];
            float gc = s->gpre[pb_b][2 * HQ + pb_j];
            float go = s->gpre[pb_b][3 * HQ + pb_j];
            float si = sig_fast(gi);
            float sf = sig_fast(gf);
            float tg = tanh_fast(gc);
            float so = sig_fast(go);
            c = sf * c + si * tg;
            float h = so * tanh_fast(c);
            s->hsh[pb_b][pb_j] = h;

            int  len = s->lsh[pb_b];
            bool wr  = dir ? (t == 0) : (t == len - 1);
            if (wr)
                g_h1last[(bbase + pb_b) * 128 + dir * HQ + pb_j] = h;
        }
#pragma unroll
        for (int b = 0; b < NB; ++b) ldc[b] = ldn[b];
    }
}

// =====================================================================
// Fused kernel: bids [0,256) = l0, [256, 16640) = gemm, [16640, 16896) = l1.
// =====================================================================
__global__ void __launch_bounds__(256, 2)
fused_kernel(const float* __restrict__ x, const int* __restrict__ lens,
             const float* __restrict__ Wih0f, const float* __restrict__ Whh0f,
             const float* __restrict__ bih0f, const float* __restrict__ bhh0f,
             const float* __restrict__ Wih0b, const float* __restrict__ Whh0b,
             const float* __restrict__ bih0b, const float* __restrict__ bhh0b,
             const float* __restrict__ Whh1f, const float* __restrict__ Whh1b,
             const float* __restrict__ bih1f, const float* __restrict__ bhh1f,
             const float* __restrict__ bih1b, const float* __restrict__ bhh1b)
{
    __shared__ __align__(16) unsigned char sraw[SMEM_BYTES];
    const int bid = blockIdx.x;
    if (bid < L0_BLOCKS) {
        l0_fn(sraw, bid, x, lens,
              Wih0f, Whh0f, bih0f, bhh0f,
              Wih0b, Whh0b, bih0b, bhh0b);
    } else if (bid < L0_BLOCKS + GEMM_BLOCKS) {
        gemm_fn(sraw, bid - L0_BLOCKS, lens, bih1f, bhh1f, bih1b, bhh1b);
    } else {
        l1_fn(sraw, bid - (L0_BLOCKS + GEMM_BLOCKS), lens, Whh1f, Whh1b);
    }
}

// =====================================================================
// Flag zeroing (runs before fused every launch)
// =====================================================================
__global__ void zero_flags_kernel()
{
    int idx = blockIdx.x * blockDim.x + threadIdx.x;
    if (idx < BQ) g_h0done[idx] = 0;
    int* tf = &g_t1flag[0][0][0];
    for (int i = idx; i < 2 * BQ * 16; i += gridDim.x * blockDim.x)
        tf[i] = 0;
}

// =====================================================================
// Wih1 transpose pre-kernel: g_WT[dir][k][g] = Wih1_dir[g][k]
// =====================================================================
__global__ void transpose_w_kernel(const float* __restrict__ WihF,
                                   const float* __restrict__ WihB)
{
    const float* W  = blockIdx.x ? WihB : WihF;
    float*       WT = g_WT[blockIdx.x];
    const int g = threadIdx.x;               // 0..255
    const float4* wrow = reinterpret_cast<const float4*>(W + (size_t)g * 128);
#pragma unroll
    for (int k4 = 0; k4 < 32; ++k4) {
        float4 v = wrow[k4];
        WT[(4 * k4 + 0) * G4 + g] = v.x;
        WT[(4 * k4 + 1) * G4 + g] = v.y;
        WT[(4 * k4 + 2) * G4 + g] = v.z;
        WT[(4 * k4 + 3) * G4 + g] = v.w;
    }
}

// =====================================================================
// Final head: FB batches per block; class range split in 2.
// =====================================================================
__global__ void __launch_bounds__(256)
final_kernel(const float* __restrict__ Wout, const float* __restrict__ bout,
             float* __restrict__ out)
{
    const int bbase = blockIdx.x * FB;
    const int chalf = blockIdx.y;
    __shared__ float hs[FB][128];
    for (int i = threadIdx.x; i < FB * 128; i += 256)
        hs[i >> 7][i & 127] = g_h1last[bbase * 128 + i];
    __syncthreads();

    const int cbeg = chalf * 549;
    const int cend = cbeg + 549;
    for (int cl = cbeg + threadIdx.x; cl < cend; cl += 256) {
        const float4* wv = reinterpret_cast<const float4*>(Wout + (size_t)cl * 128);
        float a[FB];
#pragma unroll
        for (int b = 0; b < FB; ++b) a[b] = bout[cl];
#pragma unroll
        for (int k = 0; k < 32; ++k) {
            float4 v = wv[k];
#pragma unroll
            for (int b = 0; b < FB; ++b) {
                a[b] += hs[b][4 * k + 0] * v.x + hs[b][4 * k + 1] * v.y
                      + hs[b][4 * k + 2] * v.z + hs[b][4 * k + 3] * v.w;
            }
        }
#pragma unroll
        for (int b = 0; b < FB; ++b)
            out[(size_t)(bbase + b) * NCLS + cl] = a[b];
    }
}

// =====================================================================
extern "C" void kernel_launch(void* const* d_in, const int* in_sizes, int n_in,
                              void* d_out, int out_size)
{
    const float* x     = (const float*)d_in[0];
    const int*   lens  = (const int*)  d_in[1];
    const float* Wih0f = (const float*)d_in[2];
    const float* Whh0f = (const float*)d_in[3];
    const float* bih0f = (const float*)d_in[4];
    const float* bhh0f = (const float*)d_in[5];
    const float* Wih0b = (const float*)d_in[6];
    const float* Whh0b = (const float*)d_in[7];
    const float* bih0b = (const float*)d_in[8];
    const float* bhh0b = (const float*)d_in[9];
    const float* Wih1f = (const float*)d_in[10];
    const float* Whh1f = (const float*)d_in[11];
    const float* bih1f = (const float*)d_in[12];
    const float* bhh1f = (const float*)d_in[13];
    const float* Wih1b = (const float*)d_in[14];
    const float* Whh1b = (const float*)d_in[15];
    const float* bih1b = (const float*)d_in[16];
    const float* bhh1b = (const float*)d_in[17];
    const float* Wout  = (const float*)d_in[18];
    const float* bout  = (const float*)d_in[19];

    zero_flags_kernel<<<32, 256>>>();
    transpose_w_kernel<<<2, 256>>>(Wih1f, Wih1b);

    fused_kernel<<<FUSED_GRID, 256>>>(x, lens,
                                      Wih0f, Whh0f, bih0f, bhh0f,
                                      Wih0b, Whh0b, bih0b, bhh0b,
                                      Whh1f, Whh1b,
                                      bih1f, bhh1f, bih1b, bhh1b);

    dim3 gf(BQ / FB, 2);
    final_kernel<<<gf, 256>>>(Wout, bout, (float*)d_out);
}

// round 7
// speedup vs baseline: 1.3963x; 1.3263x over previous
#include <cuda_runtime.h>
#include <math.h>

#define BQ   512
#define TQ   1024
#define DQ   4
#define HQ   64
#define G4   256          // 4*H
#define NB   4            // batches per recurrent block
#define NCLS 1098
#define FB   4            // batches per final-head block

typedef unsigned long long ull;

// ---------------- scratch (static device allocations only) ----------------
__device__ float g_g1[2][(size_t)BQ * TQ * G4];   // layer-1 gate preactivations per dir
__device__ float g_h0[(size_t)BQ * TQ * 128];     // layer-0 bidir output, [B][T][128]
__device__ float g_h1last[BQ * 128];              // gathered last timestep of layer 1

// ---------------- f32x2 packed-math helpers ----------------
__device__ __forceinline__ ull pk2(float lo, float hi) {
    ull r; asm("mov.b64 %0,{%1,%2};" : "=l"(r) : "f"(lo), "f"(hi)); return r;
}
__device__ __forceinline__ void upk2(ull v, float& lo, float& hi) {
    asm("mov.b64 {%0,%1},%2;" : "=f"(lo), "=f"(hi) : "l"(v));
}
__device__ __forceinline__ ull ffma2(ull a, ull b, ull c) {
    ull d; asm("fma.rn.f32x2 %0,%1,%2,%3;" : "=l"(d) : "l"(a), "l"(b), "l"(c)); return d;
}
__device__ __forceinline__ float tanh_fast(float x) {
    float y; asm("tanh.approx.f32 %0,%1;" : "=f"(y) : "f"(x)); return y;
}
__device__ __forceinline__ float sig_fast(float x) {
    return fmaf(0.5f, tanh_fast(0.5f * x), 0.5f);
}

// block (0..255) -> sorted group id: pairs wave-1 co-resident blocks
// (bid, bid+148) with (long, short) sequence groups.
__device__ __forceinline__ void block_to_group(int bid, int& dir, int& xb) {
    int j = (bid < 148) ? bid : (403 - bid);
    dir = j & 1;
    xb  = j >> 1;
}

// =====================================================================
// Layer 0: bidirectional LSTM, truncated at per-block max length. (R3)
// =====================================================================
__global__ void __launch_bounds__(256, 2)
lstm_l0_kernel(const float* __restrict__ x, const int* __restrict__ lens,
               const float* __restrict__ WihF, const float* __restrict__ WhhF,
               const float* __restrict__ bihF, const float* __restrict__ bhhF,
               const float* __restrict__ WihB, const float* __restrict__ WhhB,
               const float* __restrict__ bihB, const float* __restrict__ bhhB)
{
    int dir, xb;
    block_to_group(blockIdx.x, dir, xb);
    const int bbase = xb * NB;
    const int g     = threadIdx.x;            // gate row 0..255

    const float* Wih = dir ? WihB : WihF;
    const float* Whh = dir ? WhhB : WhhF;
    const float* bih = dir ? bihB : bihF;
    const float* bhh = dir ? bhhB : bhhF;

    ull whh2[HQ / 2];
    {
        const ull* wsrc = reinterpret_cast<const ull*>(Whh + (size_t)g * HQ);
#pragma unroll
        for (int k = 0; k < HQ / 2; ++k) whh2[k] = wsrc[k];
    }
    float wih[DQ];
#pragma unroll
    for (int k = 0; k < DQ; ++k) wih[k] = Wih[g * DQ + k];
    const float bias = bih[g] + bhh[g];

    __shared__ __align__(16) float hsh[NB][HQ];
    __shared__ float  gpre[NB][G4];
    __shared__ float4 xs[2][NB];
    __shared__ int    lsh[NB];

    const int pb_b = g >> 6, pb_j = g & 63;

    if (g < NB) lsh[g] = lens[bbase + g];
    hsh[pb_b][pb_j] = 0.0f;
    float c = 0.0f;
    __syncthreads();

    const int maxlen = lsh[0];                // lens sorted descending

    if (g < NB) {
        int len = lsh[g];
        int tt  = dir ? (len - 1) : 0;
        xs[0][g] = reinterpret_cast<const float4*>(x)[(size_t)(bbase + g) * TQ + tt];
    }

    for (int t = 0; t < maxlen; ++t) {
        float4 xn = make_float4(0.f, 0.f, 0.f, 0.f);
        if (g < NB) {
            int tn  = (t + 1 < maxlen) ? (t + 1) : t;
            int len = lsh[g];
            int tt  = tn;
            if (dir) tt = (tn < len) ? (len - 1 - tn) : tn;
            xn = reinterpret_cast<const float4*>(x)[(size_t)(bbase + g) * TQ + tt];
        }
        __syncthreads();

        // ---- phase A: gate preactivations (packed f32x2, LDS.128 h reads)
        float acc[NB];
#pragma unroll
        for (int b = 0; b < NB; ++b) {
            float4 xv = xs[t & 1][b];
            float base = bias + wih[0] * xv.x + wih[1] * xv.y
                              + wih[2] * xv.z + wih[3] * xv.w;
            const ulonglong2* h2 = reinterpret_cast<const ulonglong2*>(&hsh[b][0]);
            ull a0 = 0ull, a1 = 0ull;
#pragma unroll
            for (int kk = 0; kk < HQ / 4; ++kk) {
                ulonglong2 hv = h2[kk];
                a0 = ffma2(whh2[2 * kk],     hv.x, a0);
                a1 = ffma2(whh2[2 * kk + 1], hv.y, a1);
            }
            float l0, u0, l1, u1;
            upk2(a0, l0, u0); upk2(a1, l1, u1);
            acc[b] = base + ((l0 + u0) + (l1 + u1));
        }
#pragma unroll
        for (int b = 0; b < NB; ++b) gpre[b][g] = acc[b];
        __syncthreads();

        // ---- phase B: pointwise cell update
        {
            float gi = gpre[pb_b][pb_j];
            float gf = gpre[pb_b][HQ + pb_j];
            float gc = gpre[pb_b][2 * HQ + pb_j];
            float go = gpre[pb_b][3 * HQ + pb_j];
            float si = sig_fast(gi);
            float sf = sig_fast(gf);
            float tg = tanh_fast(gc);
            float so = sig_fast(go);
            c = sf * c + si * tg;
            float h = so * tanh_fast(c);
            hsh[pb_b][pb_j] = h;

            int len = lsh[pb_b];
            int ts  = t;
            if (dir) ts = (t < len) ? (len - 1 - t) : t;
            g_h0[((size_t)(bbase + pb_b) * TQ + ts) * 128 + dir * HQ + pb_j] = h;
        }
        if (g < NB) xs[(t + 1) & 1][g] = xn;
    }
}

// =====================================================================
// Layer-1 gate GEMM on tensor cores: mma.sync m16n8k8 tf32.
//   C[64 rows][256 gates] = A[64][128] . W^T, W native [gate][k] row-major
//   = B col-major, so no transpose needed. Bias folded into C init.
// Block: 256 thr / 8 warps; warp (wr=w&3, wc=w>>2) owns rows 16*wr..+15,
// cols 128*wc..+127 (16 n8 tiles). K in 4 chunks of 32 staged in smem.
// Tiles entirely past the sequence end exit immediately.
// =====================================================================
#define GM_ROWS   64
#define AS_STRIDE 132            // 64x132 floats (pad -> conflict-free frags)
#define WS_STRIDE 36             // 256x36  floats
#define GEMM_SMEM ((64 * AS_STRIDE + 256 * WS_STRIDE) * 4)   // 70656 B

__device__ __forceinline__ void mma_tf32(float* c, const unsigned* a, unsigned b0, unsigned b1) {
    asm volatile(
        "mma.sync.aligned.m16n8k8.row.col.f32.tf32.tf32.f32 "
        "{%0,%1,%2,%3},{%4,%5,%6,%7},{%8,%9},{%0,%1,%2,%3};"
        : "+f"(c[0]), "+f"(c[1]), "+f"(c[2]), "+f"(c[3])
        : "r"(a[0]), "r"(a[1]), "r"(a[2]), "r"(a[3]), "r"(b0), "r"(b1));
}

__global__ void __launch_bounds__(256, 2)
gates1_gemm_kernel(const int* __restrict__ lens,
                   const float* __restrict__ WihF, const float* __restrict__ WihB,
                   const float* __restrict__ bihF, const float* __restrict__ bhhF,
                   const float* __restrict__ bihB, const float* __restrict__ bhhB)
{
    const int tile  = blockIdx.x;
    const int b     = blockIdx.y;
    const int dir   = blockIdx.z;
    const int tbase = tile * GM_ROWS;

    const int len = lens[b];
    if (tbase >= len) return;                 // rows >= len are never consumed

    extern __shared__ float sm[];
    float* As = sm;                           // [64][AS_STRIDE]
    float* Ws = sm + 64 * AS_STRIDE;          // [256][WS_STRIDE]

    const int tid  = threadIdx.x;
    const int lane = tid & 31;
    const int w    = tid >> 5;
    const int wr   = w & 3;                   // row-group 0..3
    const int wc   = w >> 2;                  // col-half 0..1
    const int gid  = lane >> 2;               // 0..7
    const int tig  = lane & 3;                // 0..3

    const float* Wih = dir ? WihB : WihF;
    const float* bih = dir ? bihB : bihF;
    const float* bhh = dir ? bhhB : bhhF;

    // ---- C accumulators initialized with bias (c0,c1 = cols n0+2tig, +1)
    float acc[16][4];
#pragma unroll
    for (int nt = 0; nt < 16; ++nt) {
        int col0 = wc * 128 + nt * 8 + 2 * tig;
        float bv0 = bih[col0]     + bhh[col0];
        float bv1 = bih[col0 + 1] + bhh[col0 + 1];
        acc[nt][0] = bv0; acc[nt][1] = bv1;
        acc[nt][2] = bv0; acc[nt][3] = bv1;
    }

    // ---- A tile: 64 rows x 128 k (row gather handles backward reversal)
    const float* h0b = g_h0 + (size_t)b * TQ * 128;
#pragma unroll
    for (int i = 0; i < 8; ++i) {
        int idx = tid + 256 * i;              // 0..2047 float4 slots
        int r   = idx >> 5, kq = idx & 31;
        int srow = tbase + r;
        if (dir) srow = (srow < len) ? (len - 1 - srow) : srow;
        float4 v = *reinterpret_cast<const float4*>(h0b + (size_t)srow * 128 + 4 * kq);
        *reinterpret_cast<float4*>(&As[r * AS_STRIDE + 4 * kq]) = v;
    }

    const int r0 = wr * 16 + gid;             // A-frag base row

    for (int k0 = 0; k0 < 128; k0 += 32) {
        // ---- W chunk: Ws[n][kloc] <- Wih[n][k0+kloc], n-major
        __syncthreads();                      // orders As stores (iter 0) / Ws reuse
#pragma unroll
        for (int i = 0; i < 8; ++i) {
            int idx = tid + 256 * i;          // 0..2047 float4 slots
            int n   = idx >> 3, kq = idx & 7;
            float4 v = *reinterpret_cast<const float4*>(Wih + (size_t)n * 128 + k0 + 4 * kq);
            *reinterpret_cast<float4*>(&Ws[n * WS_STRIDE + 4 * kq]) = v;
        }
        __syncthreads();

#pragma unroll
        for (int ks = 0; ks < 4; ++ks) {
            const int kl = ks * 8;
            unsigned a[4];
            a[0] = __float_as_uint(As[r0 * AS_STRIDE + k0 + kl + tig]);
            a[1] = __float_as_uint(As[(r0 + 8) * AS_STRIDE + k0 + kl + tig]);
            a[2] = __float_as_uint(As[r0 * AS_STRIDE + k0 + kl + 4 + tig]);
            a[3] = __float_as_uint(As[(r0 + 8) * AS_STRIDE + k0 + kl + 4 + tig]);
#pragma unroll
            for (int nt = 0; nt < 16; ++nt) {
                int n = wc * 128 + nt * 8 + gid;
                unsigned b0 = __float_as_uint(Ws[n * WS_STRIDE + kl + tig]);
                unsigned b1 = __float_as_uint(Ws[n * WS_STRIDE + kl + 4 + tig]);
                mma_tf32(acc[nt], a, b0, b1);
            }
        }
    }

    // ---- epilogue: float2 stores (c0,c1)->(row r0), (c2,c3)->(row r0+8)
    float* outp = g_g1[dir] + ((size_t)b * TQ + tbase) * G4;
#pragma unroll
    for (int nt = 0; nt < 16; ++nt) {
        int col0 = wc * 128 + nt * 8 + 2 * tig;
        *reinterpret_cast<float2*>(outp + (size_t)r0 * G4 + col0) =
            make_float2(acc[nt][0], acc[nt][1]);
        *reinterpret_cast<float2*>(outp + (size_t)(r0 + 8) * G4 + col0) =
            make_float2(acc[nt][2], acc[nt][3]);
    }
}

// =====================================================================
// Layer 1: recurrent loop over precomputed gate preactivations. (R3)
// =====================================================================
__global__ void __launch_bounds__(256, 2)
lstm_l1_kernel(const int* __restrict__ lens,
               const float* __restrict__ WhhF, const float* __restrict__ WhhB)
{
    int dir, xb;
    block_to_group(blockIdx.x, dir, xb);
    const int bbase = xb * NB;
    const int g     = threadIdx.x;

    const float* Whh = dir ? WhhB : WhhF;
    const float* gin = g_g1[dir];

    ull whh2[HQ / 2];
    {
        const ull* wsrc = reinterpret_cast<const ull*>(Whh + (size_t)g * HQ);
#pragma unroll
        for (int k = 0; k < HQ / 2; ++k) whh2[k] = wsrc[k];
    }

    __shared__ __align__(16) float hsh[NB][HQ];
    __shared__ float gpre[NB][G4];
    __shared__ int   lsh[NB];

    const int pb_b = g >> 6, pb_j = g & 63;
    if (g < NB) lsh[g] = lens[bbase + g];
    hsh[pb_b][pb_j] = 0.0f;
    float c = 0.0f;
    __syncthreads();

    const int maxlen = lsh[0];

    float ldc[NB];
#pragma unroll
    for (int b = 0; b < NB; ++b)
        ldc[b] = gin[((size_t)(bbase + b) * TQ) * G4 + g];

    for (int t = 0; t < maxlen; ++t) {
        float ldn[NB];
        const int tn = (t + 1 < maxlen) ? (t + 1) : t;
#pragma unroll
        for (int b = 0; b < NB; ++b)
            ldn[b] = gin[((size_t)(bbase + b) * TQ + tn) * G4 + g];

        __syncthreads();

        float acc[NB];
#pragma unroll
        for (int b = 0; b < NB; ++b) {
            const ulonglong2* h2 = reinterpret_cast<const ulonglong2*>(&hsh[b][0]);
            ull a0 = 0ull, a1 = 0ull;
#pragma unroll
            for (int kk = 0; kk < HQ / 4; ++kk) {
                ulonglong2 hv = h2[kk];
                a0 = ffma2(whh2[2 * kk],     hv.x, a0);
                a1 = ffma2(whh2[2 * kk + 1], hv.y, a1);
            }
            float l0, u0, l1, u1;
            upk2(a0, l0, u0); upk2(a1, l1, u1);
            acc[b] = ldc[b] + ((l0 + u0) + (l1 + u1));
        }
#pragma unroll
        for (int b = 0; b < NB; ++b) gpre[b][g] = acc[b];
        __syncthreads();

        {
            float gi = gpre[pb_b][pb_j];
            float gf = gpre[pb_b][HQ + pb_j];
            float gc = gpre[pb_b][2 * HQ + pb_j];
            float go = gpre[pb_b][3 * HQ + pb_j];
            float si = sig_fast(gi);
            float sf = sig_fast(gf);
            float tg = tanh_fast(gc);
            float so = sig_fast(go);
            c = sf * c + si * tg;
            float h = so * tanh_fast(c);
            hsh[pb_b][pb_j] = h;

            int  len = lsh[pb_b];
            bool wr  = dir ? (t == 0) : (t == len - 1);
            if (wr)
                g_h1last[(bbase + pb_b) * 128 + dir * HQ + pb_j] = h;
        }
#pragma unroll
        for (int b = 0; b < NB; ++b) ldc[b] = ldn[b];
    }
}

// =====================================================================
// Final head: FB batches per block; class range split in 2.
// =====================================================================
__global__ void __launch_bounds__(256)
final_kernel(const float* __restrict__ Wout, const float* __restrict__ bout,
             float* __restrict__ out)
{
    const int bbase = blockIdx.x * FB;
    const int chalf = blockIdx.y;
    __shared__ float hs[FB][128];
    for (int i = threadIdx.x; i < FB * 128; i += 256)
        hs[i >> 7][i & 127] = g_h1last[bbase * 128 + i];
    __syncthreads();

    const int cbeg = chalf * 549;
    const int cend = cbeg + 549;
    for (int cl = cbeg + threadIdx.x; cl < cend; cl += 256) {
        const float4* wv = reinterpret_cast<const float4*>(Wout + (size_t)cl * 128);
        float a[FB];
#pragma unroll
        for (int b = 0; b < FB; ++b) a[b] = bout[cl];
#pragma unroll
        for (int k = 0; k < 32; ++k) {
            float4 v = wv[k];
#pragma unroll
            for (int b = 0; b < FB; ++b) {
                a[b] += hs[b][4 * k + 0] * v.x + hs[b][4 * k + 1] * v.y
                      + hs[b][4 * k + 2] * v.z + hs[b][4 * k + 3] * v.w;
            }
        }
#pragma unroll
        for (int b = 0; b < FB; ++b)
            out[(size_t)(bbase + b) * NCLS + cl] = a[b];
    }
}

// =====================================================================
extern "C" void kernel_launch(void* const* d_in, const int* in_sizes, int n_in,
                              void* d_out, int out_size)
{
    const float* x     = (const float*)d_in[0];
    const int*   lens  = (const int*)  d_in[1];
    const float* Wih0f = (const float*)d_in[2];
    const float* Whh0f = (const float*)d_in[3];
    const float* bih0f = (const float*)d_in[4];
    const float* bhh0f = (const float*)d_in[5];
    const float* Wih0b = (const float*)d_in[6];
    const float* Whh0b = (const float*)d_in[7];
    const float* bih0b = (const float*)d_in[8];
    const float* bhh0b = (const float*)d_in[9];
    const float* Wih1f = (const float*)d_in[10];
    const float* Whh1f = (const float*)d_in[11];
    const float* bih1f = (const float*)d_in[12];
    const float* bhh1f = (const float*)d_in[13];
    const float* Wih1b = (const float*)d_in[14];
    const float* Whh1b = (const float*)d_in[15];
    const float* bih1b = (const float*)d_in[16];
    const float* bhh1b = (const float*)d_in[17];
    const float* Wout  = (const float*)d_in[18];
    const float* bout  = (const float*)d_in[19];

    static bool attr_set = false;
    if (!attr_set) {
        cudaFuncSetAttribute(gates1_gemm_kernel,
                             cudaFuncAttributeMaxDynamicSharedMemorySize, GEMM_SMEM);
        attr_set = true;
    }

    lstm_l0_kernel<<<256, 256>>>(x, lens,
                                 Wih0f, Whh0f, bih0f, bhh0f,
                                 Wih0b, Whh0b, bih0b, bhh0b);

    dim3 gg(TQ / GM_ROWS, BQ, 2);
    gates1_gemm_kernel<<<gg, 256, GEMM_SMEM>>>(lens, Wih1f, Wih1b,
                                               bih1f, bhh1f, bih1b, bhh1b);

    lstm_l1_kernel<<<256, 256>>>(lens, Whh1f, Whh1b);

    dim3 gf(BQ / FB, 2);
    final_kernel<<<gf, 256>>>(Wout, bout, (float*)d_out);
}

// round 8
// speedup vs baseline: 2.0058x; 1.4365x over previous
#include <cuda_runtime.h>
#include <math.h>

#define BQ   512
#define TQ   1024
#define DQ   4
#define HQ   64
#define G4   256          // 4*H
#define NB   4            // batches per recurrent block
#define NCLS 1098
#define FB   4            // batches per final-head block

#define HX_STRIDE 72      // [h(64) | x(4) | 1 | 0 0 0]; 72 -> banks 0/8/16/24
#define GP_STRIDE 6       // gpre[gate][batch] stride (even -> aligned float2)

// ---------------- scratch (static device allocations only) ----------------
__device__ float g_g1[2][(size_t)BQ * TQ * G4];   // layer-1 gate preactivations per dir
__device__ float g_h0[(size_t)BQ * TQ * 128];     // layer-0 bidir output, [B][T][128]
__device__ float g_h1last[BQ * 128];              // gathered last timestep of layer 1

// ---------------- helpers ----------------
__device__ __forceinline__ float tanh_fast(float x) {
    float y; asm("tanh.approx.f32 %0,%1;" : "=f"(y) : "f"(x)); return y;
}
__device__ __forceinline__ float sig_fast(float x) {
    return fmaf(0.5f, tanh_fast(0.5f * x), 0.5f);
}
__device__ __forceinline__ unsigned tf32_rna(float v) {
    unsigned y; asm("cvt.rna.tf32.f32 %0,%1;" : "=r"(y) : "f"(v)); return y;
}
__device__ __forceinline__ void mma_tf32(float* c, const unsigned* a, unsigned b0, unsigned b1) {
    asm volatile(
        "mma.sync.aligned.m16n8k8.row.col.f32.tf32.tf32.f32 "
        "{%0,%1,%2,%3},{%4,%5,%6,%7},{%8,%9},{%0,%1,%2,%3};"
        : "+f"(c[0]), "+f"(c[1]), "+f"(c[2]), "+f"(c[3])
        : "r"(a[0]), "r"(a[1]), "r"(a[2]), "r"(a[3]), "r"(b0), "r"(b1));
}

// block (0..255) -> sorted group id: pairs wave-1 co-resident blocks
// (bid, bid+148) with (long, short) sequence groups.
__device__ __forceinline__ void block_to_group(int bid, int& dir, int& xb) {
    int j = (bid < 148) ? bid : (403 - bid);
    dir = j & 1;
    xb  = j >> 1;
}

// =====================================================================
// Layer 0: bidirectional LSTM; recurrent matvec on tensor cores.
// D[256 gates, 8 cols(batch 0-3 real)] = A[256 x 72] . B[72 x 8]
//   A rows = [Whh | Wih | bias | 0 0 0] (reg-resident tf32 frags)
//   B cols = hx[batch] = [h | x | 1 | 0 0 0] (smem, rebuilt per step)
// Warp w owns gate m-tiles 2w, 2w+1 (gates 32w..32w+31).
// =====================================================================
__global__ void __launch_bounds__(256, 2)
lstm_l0_kernel(const float* __restrict__ x, const int* __restrict__ lens,
               const float* __restrict__ WihF, const float* __restrict__ WhhF,
               const float* __restrict__ bihF, const float* __restrict__ bhhF,
               const float* __restrict__ WihB, const float* __restrict__ WhhB,
               const float* __restrict__ bihB, const float* __restrict__ bhhB)
{
    int dir, xb;
    block_to_group(blockIdx.x, dir, xb);
    const int bbase = xb * NB;
    const int tid  = threadIdx.x;
    const int w    = tid >> 5;
    const int lane = tid & 31;
    const int gid  = lane >> 2;               // 0..7
    const int tig  = lane & 3;                // 0..3

    const float* Wih = dir ? WihB : WihF;
    const float* Whh = dir ? WhhB : WhhF;
    const float* bih = dir ? bihB : bihF;
    const float* bhh = dir ? bhhB : bhhF;

    // ---- A fragments: [mt][kc][4], gates on M, K = 72 augmented
    unsigned afr[2][9][4];
#pragma unroll
    for (int mt = 0; mt < 2; ++mt) {
#pragma unroll
        for (int kc = 0; kc < 9; ++kc) {
#pragma unroll
            for (int e = 0; e < 4; ++e) {
                int g = w * 32 + mt * 16 + gid + ((e & 1) ? 8 : 0);
                int k = kc * 8 + tig + ((e & 2) ? 4 : 0);
                float v;
                if (k < 64)       v = Whh[g * HQ + k];
                else if (k < 68)  v = Wih[g * DQ + (k - 64)];
                else if (k == 68) v = bih[g] + bhh[g];
                else              v = 0.0f;
                afr[mt][kc][e] = tf32_rna(v);
            }
        }
    }

    __shared__ float hx[NB][HX_STRIDE];
    __shared__ float gpre[G4 * GP_STRIDE];
    __shared__ int   lsh[NB];

    const int pb_b = tid >> 6, pb_j = tid & 63;

    if (tid < NB) lsh[tid] = lens[bbase + tid];
    hx[pb_b][pb_j] = 0.0f;                    // h part
    if (tid < NB) {                           // constant tail
        hx[tid][68] = 1.0f;
        hx[tid][69] = 0.0f; hx[tid][70] = 0.0f; hx[tid][71] = 0.0f;
    }
    float c = 0.0f;
    __syncthreads();

    const int maxlen = lsh[0];                // lens sorted descending

    // x(t=0)
    if (tid < NB) {
        int len = lsh[tid];
        int tt  = dir ? (len - 1) : 0;
        float4 xv = reinterpret_cast<const float4*>(x)[(size_t)(bbase + tid) * TQ + tt];
        hx[tid][64] = xv.x; hx[tid][65] = xv.y; hx[tid][66] = xv.z; hx[tid][67] = xv.w;
    }
    __syncthreads();

    const float* hxb = &hx[gid & 3][0];

    for (int t = 0; t < maxlen; ++t) {
        // prefetch x(t+1) into regs (overlaps MMA)
        float4 xn = make_float4(0.f, 0.f, 0.f, 0.f);
        if (tid < NB) {
            int tn  = (t + 1 < maxlen) ? (t + 1) : t;
            int len = lsh[tid];
            int tt  = tn;
            if (dir) tt = (tn < len) ? (len - 1 - tn) : tn;
            xn = reinterpret_cast<const float4*>(x)[(size_t)(bbase + tid) * TQ + tt];
        }

        // ---- phase A: tensor-core matvec
        float acc0[4] = {0.f, 0.f, 0.f, 0.f};
        float acc1[4] = {0.f, 0.f, 0.f, 0.f};
#pragma unroll
        for (int kc = 0; kc < 9; ++kc) {
            unsigned b0 = __float_as_uint(hxb[kc * 8 + tig]);
            unsigned b1 = __float_as_uint(hxb[kc * 8 + 4 + tig]);
            mma_tf32(acc0, afr[0][kc], b0, b1);
            mma_tf32(acc1, afr[1][kc], b0, b1);
        }
        if (tig < 2) {
            int g0 = w * 32 + gid;
            *reinterpret_cast<float2*>(&gpre[g0 * GP_STRIDE + 2 * tig]) =
                make_float2(acc0[0], acc0[1]);
            *reinterpret_cast<float2*>(&gpre[(g0 + 8) * GP_STRIDE + 2 * tig]) =
                make_float2(acc0[2], acc0[3]);
            *reinterpret_cast<float2*>(&gpre[(g0 + 16) * GP_STRIDE + 2 * tig]) =
                make_float2(acc1[0], acc1[1]);
            *reinterpret_cast<float2*>(&gpre[(g0 + 24) * GP_STRIDE + 2 * tig]) =
                make_float2(acc1[2], acc1[3]);
        }
        __syncthreads();

        // ---- phase B: pointwise cell update for (pb_b, pb_j)
        {
            float gi = gpre[(pb_j)       * GP_STRIDE + pb_b];
            float gf = gpre[(64  + pb_j) * GP_STRIDE + pb_b];
            float gc = gpre[(128 + pb_j) * GP_STRIDE + pb_b];
            float go = gpre[(192 + pb_j) * GP_STRIDE + pb_b];
            float si = sig_fast(gi);
            float sf = sig_fast(gf);
            float tg = tanh_fast(gc);
            float so = sig_fast(go);
            c = sf * c + si * tg;
            float h = so * tanh_fast(c);
            hx[pb_b][pb_j] = h;

            int len = lsh[pb_b];
            int ts  = t;
            if (dir) ts = (t < len) ? (len - 1 - t) : t;
            g_h0[((size_t)(bbase + pb_b) * TQ + ts) * 128 + dir * HQ + pb_j] = h;
        }
        if (tid < NB) {
            hx[tid][64] = xn.x; hx[tid][65] = xn.y;
            hx[tid][66] = xn.z; hx[tid][67] = xn.w;
        }
        __syncthreads();
    }
}

// =====================================================================
// Layer-1 gate GEMM on tensor cores (R7, unchanged).
// =====================================================================
#define GM_ROWS   64
#define AS_STRIDE 132
#define WS_STRIDE 36
#define GEMM_SMEM ((64 * AS_STRIDE + 256 * WS_STRIDE) * 4)   // 70656 B

__global__ void __launch_bounds__(256, 2)
gates1_gemm_kernel(const int* __restrict__ lens,
                   const float* __restrict__ WihF, const float* __restrict__ WihB,
                   const float* __restrict__ bihF, const float* __restrict__ bhhF,
                   const float* __restrict__ bihB, const float* __restrict__ bhhB)
{
    const int tile  = blockIdx.x;
    const int b     = blockIdx.y;
    const int dir   = blockIdx.z;
    const int tbase = tile * GM_ROWS;

    const int len = lens[b];
    if (tbase >= len) return;

    extern __shared__ float sm[];
    float* As = sm;
    float* Ws = sm + 64 * AS_STRIDE;

    const int tid  = threadIdx.x;
    const int lane = tid & 31;
    const int w    = tid >> 5;
    const int wr   = w & 3;
    const int wc   = w >> 2;
    const int gid  = lane >> 2;
    const int tig  = lane & 3;

    const float* Wih = dir ? WihB : WihF;
    const float* bih = dir ? bihB : bihF;
    const float* bhh = dir ? bhhB : bhhF;

    float acc[16][4];
#pragma unroll
    for (int nt = 0; nt < 16; ++nt) {
        int col0 = wc * 128 + nt * 8 + 2 * tig;
        float bv0 = bih[col0]     + bhh[col0];
        float bv1 = bih[col0 + 1] + bhh[col0 + 1];
        acc[nt][0] = bv0; acc[nt][1] = bv1;
        acc[nt][2] = bv0; acc[nt][3] = bv1;
    }

    const float* h0b = g_h0 + (size_t)b * TQ * 128;
#pragma unroll
    for (int i = 0; i < 8; ++i) {
        int idx = tid + 256 * i;
        int r   = idx >> 5, kq = idx & 31;
        int srow = tbase + r;
        if (dir) srow = (srow < len) ? (len - 1 - srow) : srow;
        float4 v = *reinterpret_cast<const float4*>(h0b + (size_t)srow * 128 + 4 * kq);
        *reinterpret_cast<float4*>(&As[r * AS_STRIDE + 4 * kq]) = v;
    }

    const int r0 = wr * 16 + gid;

    for (int k0 = 0; k0 < 128; k0 += 32) {
        __syncthreads();
#pragma unroll
        for (int i = 0; i < 8; ++i) {
            int idx = tid + 256 * i;
            int n   = idx >> 3, kq = idx & 7;
            float4 v = *reinterpret_cast<const float4*>(Wih + (size_t)n * 128 + k0 + 4 * kq);
            *reinterpret_cast<float4*>(&Ws[n * WS_STRIDE + 4 * kq]) = v;
        }
        __syncthreads();

#pragma unroll
        for (int ks = 0; ks < 4; ++ks) {
            const int kl = ks * 8;
            unsigned a[4];
            a[0] = __float_as_uint(As[r0 * AS_STRIDE + k0 + kl + tig]);
            a[1] = __float_as_uint(As[(r0 + 8) * AS_STRIDE + k0 + kl + tig]);
            a[2] = __float_as_uint(As[r0 * AS_STRIDE + k0 + kl + 4 + tig]);
            a[3] = __float_as_uint(As[(r0 + 8) * AS_STRIDE + k0 + kl + 4 + tig]);
#pragma unroll
            for (int nt = 0; nt < 16; ++nt) {
                int n = wc * 128 + nt * 8 + gid;
                unsigned b0 = __float_as_uint(Ws[n * WS_STRIDE + kl + tig]);
                unsigned b1 = __float_as_uint(Ws[n * WS_STRIDE + kl + 4 + tig]);
                mma_tf32(acc[nt], a, b0, b1);
            }
        }
    }

    float* outp = g_g1[dir] + ((size_t)b * TQ + tbase) * G4;
#pragma unroll
    for (int nt = 0; nt < 16; ++nt) {
        int col0 = wc * 128 + nt * 8 + 2 * tig;
        *reinterpret_cast<float2*>(outp + (size_t)r0 * G4 + col0) =
            make_float2(acc[nt][0], acc[nt][1]);
        *reinterpret_cast<float2*>(outp + (size_t)(r0 + 8) * G4 + col0) =
            make_float2(acc[nt][2], acc[nt][3]);
    }
}

// =====================================================================
// Layer 1: recurrent over precomputed gates; h.Whh^T on tensor cores.
// Gate preactivations from g_g1 added in phase B (coalesced prefetch).
// =====================================================================
__global__ void __launch_bounds__(256, 2)
lstm_l1_kernel(const int* __restrict__ lens,
               const float* __restrict__ WhhF, const float* __restrict__ WhhB)
{
    int dir, xb;
    block_to_group(blockIdx.x, dir, xb);
    const int bbase = xb * NB;
    const int tid  = threadIdx.x;
    const int w    = tid >> 5;
    const int lane = tid & 31;
    const int gid  = lane >> 2;
    const int tig  = lane & 3;

    const float* Whh = dir ? WhhB : WhhF;
    const float* gin = g_g1[dir];

    // ---- A fragments: Whh only, K = 64
    unsigned afr[2][8][4];
#pragma unroll
    for (int mt = 0; mt < 2; ++mt) {
#pragma unroll
        for (int kc = 0; kc < 8; ++kc) {
#pragma unroll
            for (int e = 0; e < 4; ++e) {
                int g = w * 32 + mt * 16 + gid + ((e & 1) ? 8 : 0);
                int k = kc * 8 + tig + ((e & 2) ? 4 : 0);
                afr[mt][kc][e] = tf32_rna(Whh[g * HQ + k]);
            }
        }
    }

    __shared__ float hx[NB][HX_STRIDE];
    __shared__ float gpre[G4 * GP_STRIDE];
    __shared__ int   lsh[NB];

    const int pb_b = tid >> 6, pb_j = tid & 63;
    if (tid < NB) lsh[tid] = lens[bbase + tid];
    hx[pb_b][pb_j] = 0.0f;
    float c = 0.0f;
    __syncthreads();

    const int maxlen = lsh[0];
    const float* hxb = &hx[gid & 3][0];

    // per-thread gate-preact stream for phase-B role (pb_b, pb_j)
    const float* gsrc = gin + (size_t)(bbase + pb_b) * TQ * G4 + pb_j;

    float ldc[4];
#pragma unroll
    for (int q = 0; q < 4; ++q) ldc[q] = gsrc[q * 64];

    for (int t = 0; t < maxlen; ++t) {
        float ldn[4];
        const int tn = (t + 1 < maxlen) ? (t + 1) : t;
#pragma unroll
        for (int q = 0; q < 4; ++q) ldn[q] = gsrc[(size_t)tn * G4 + q * 64];

        // ---- phase A: tensor-core matvec
        float acc0[4] = {0.f, 0.f, 0.f, 0.f};
        float acc1[4] = {0.f, 0.f, 0.f, 0.f};
#pragma unroll
        for (int kc = 0; kc < 8; ++kc) {
            unsigned b0 = __float_as_uint(hxb[kc * 8 + tig]);
            unsigned b1 = __float_as_uint(hxb[kc * 8 + 4 + tig]);
            mma_tf32(acc0, afr[0][kc], b0, b1);
            mma_tf32(acc1, afr[1][kc], b0, b1);
        }
        if (tig < 2) {
            int g0 = w * 32 + gid;
            *reinterpret_cast<float2*>(&gpre[g0 * GP_STRIDE + 2 * tig]) =
                make_float2(acc0[0], acc0[1]);
            *reinterpret_cast<float2*>(&gpre[(g0 + 8) * GP_STRIDE + 2 * tig]) =
                make_float2(acc0[2], acc0[3]);
            *reinterpret_cast<float2*>(&gpre[(g0 + 16) * GP_STRIDE + 2 * tig]) =
                make_float2(acc1[0], acc1[1]);
            *reinterpret_cast<float2*>(&gpre[(g0 + 24) * GP_STRIDE + 2 * tig]) =
                make_float2(acc1[2], acc1[3]);
        }
        __syncthreads();

        // ---- phase B
        {
            float gi = gpre[(pb_j)       * GP_STRIDE + pb_b] + ldc[0];
            float gf = gpre[(64  + pb_j) * GP_STRIDE + pb_b] + ldc[1];
            float gc = gpre[(128 + pb_j) * GP_STRIDE + pb_b] + ldc[2];
            float go = gpre[(192 + pb_j) * GP_STRIDE + pb_b] + ldc[3];
            float si = sig_fast(gi);
            float sf = sig_fast(gf);
            float tg = tanh_fast(gc);
            float so = sig_fast(go);
            c = sf * c + si * tg;
            float h = so * tanh_fast(c);
            hx[pb_b][pb_j] = h;

            int  len = lsh[pb_b];
            bool wr  = dir ? (t == 0) : (t == len - 1);
            if (wr)
                g_h1last[(bbase + pb_b) * 128 + dir * HQ + pb_j] = h;
        }
#pragma unroll
        for (int q = 0; q < 4; ++q) ldc[q] = ldn[q];
        __syncthreads();
    }
}

// =====================================================================
// Final head: FB batches per block; class range split in 2.
// =====================================================================
__global__ void __launch_bounds__(256)
final_kernel(const float* __restrict__ Wout, const float* __restrict__ bout,
             float* __restrict__ out)
{
    const int bbase = blockIdx.x * FB;
    const int chalf = blockIdx.y;
    __shared__ float hs[FB][128];
    for (int i = threadIdx.x; i < FB * 128; i += 256)
        hs[i >> 7][i & 127] = g_h1last[bbase * 128 + i];
    __syncthreads();

    const int cbeg = chalf * 549;
    const int cend = cbeg + 549;
    for (int cl = cbeg + threadIdx.x; cl < cend; cl += 256) {
        const float4* wv = reinterpret_cast<const float4*>(Wout + (size_t)cl * 128);
        float a[FB];
#pragma unroll
        for (int b = 0; b < FB; ++b) a[b] = bout[cl];
#pragma unroll
        for (int k = 0; k < 32; ++k) {
            float4 v = wv[k];
#pragma unroll
            for (int b = 0; b < FB; ++b) {
                a[b] += hs[b][4 * k + 0] * v.x + hs[b][4 * k + 1] * v.y
                      + hs[b][4 * k + 2] * v.z + hs[b][4 * k + 3] * v.w;
            }
        }
#pragma unroll
        for (int b = 0; b < FB; ++b)
            out[(size_t)(bbase + b) * NCLS + cl] = a[b];
    }
}

// =====================================================================
extern "C" void kernel_launch(void* const* d_in, const int* in_sizes, int n_in,
                              void* d_out, int out_size)
{
    const float* x     = (const float*)d_in[0];
    const int*   lens  = (const int*)  d_in[1];
    const float* Wih0f = (const float*)d_in[2];
    const float* Whh0f = (const float*)d_in[3];
    const float* bih0f = (const float*)d_in[4];
    const float* bhh0f = (const float*)d_in[5];
    const float* Wih0b = (const float*)d_in[6];
    const float* Whh0b = (const float*)d_in[7];
    const float* bih0b = (const float*)d_in[8];
    const float* bhh0b = (const float*)d_in[9];
    const float* Wih1f = (const float*)d_in[10];
    const float* Whh1f = (const float*)d_in[11];
    const float* bih1f = (const float*)d_in[12];
    const float* bhh1f = (const float*)d_in[13];
    const float* Wih1b = (const float*)d_in[14];
    const float* Whh1b = (const float*)d_in[15];
    const float* bih1b = (const float*)d_in[16];
    const float* bhh1b = (const float*)d_in[17];
    const float* Wout  = (const float*)d_in[18];
    const float* bout  = (const float*)d_in[19];

    static bool attr_set = false;
    if (!attr_set) {
        cudaFuncSetAttribute(gates1_gemm_kernel,
                             cudaFuncAttributeMaxDynamicSharedMemorySize, GEMM_SMEM);
        attr_set = true;
    }

    lstm_l0_kernel<<<256, 256>>>(x, lens,
                                 Wih0f, Whh0f, bih0f, bhh0f,
                                 Wih0b, Whh0b, bih0b, bhh0b);

    dim3 gg(TQ / GM_ROWS, BQ, 2);
    gates1_gemm_kernel<<<gg, 256, GEMM_SMEM>>>(lens, Wih1f, Wih1b,
                                               bih1f, bhh1f, bih1b, bhh1b);

    lstm_l1_kernel<<<256, 256>>>(lens, Whh1f, Whh1b);

    dim3 gf(BQ / FB, 2);
    final_kernel<<<gf, 256>>>(Wout, bout, (float*)d_out);
}